// round 16
// baseline (speedup 1.0000x reference)
#include <cuda_runtime.h>
#include <cstdint>
#include <cstddef>

// ---------------------------------------------------------------------------
// Problem constants
// ---------------------------------------------------------------------------
#define B_   32
#define S_   512
#define D_   512
#define H_   8
#define L_   4
#define F_   2048
#define DK_  64
#define MROWS (B_ * S_)            // 16384 token rows

#define LDDP (L_ * D_ * D_ / 2)    // pairs in one L-stack of DxD weights
#define LFDP (L_ * F_ * D_ / 2)    // pairs in one L-stack of FxD weights
#define WPAIRS (3 * LDDP + 2 * LFDP)

// ---------------------------------------------------------------------------
// Scratch (static device arrays: no allocations allowed)
// ---------------------------------------------------------------------------
__device__ float g_x  [MROWS * D_];   // residual stream fp32
__device__ float g_o  [MROWS * D_];   // gemm outputs pre-LN
// split-bf16 planes, layout [row][kpair] u32 (bf16x2, even k in low half):
__device__ uint32_t g_xh[MROWS * (D_/2)], g_xl[MROWS * (D_/2)];
__device__ uint32_t g_yh[MROWS * (D_/2)], g_yl[MROWS * (D_/2)];
__device__ uint32_t g_kh[MROWS * (D_/2)], g_kl[MROWS * (D_/2)];   // kq planes
__device__ uint32_t g_vh[MROWS * (D_/2)], g_vl[MROWS * (D_/2)];   // v planes
__device__ uint32_t g_ch[MROWS * (D_/2)], g_cl[MROWS * (D_/2)];   // ctx planes
__device__ uint32_t g_hh[MROWS * (F_/2)], g_hl[MROWS * (F_/2)];   // ffn hidden
__device__ uint32_t g_wAh[WPAIRS], g_wAl[WPAIRS];                 // weights

// ---------------------------------------------------------------------------
// Helpers
// ---------------------------------------------------------------------------
#define MMA_BF16(c, a, b)                                                    \
    asm volatile(                                                            \
        "mma.sync.aligned.m16n8k16.row.col.f32.bf16.bf16.f32 "               \
        "{%0,%1,%2,%3},{%4,%5,%6,%7},{%8,%9},{%0,%1,%2,%3};"                 \
        : "+f"((c)[0]), "+f"((c)[1]), "+f"((c)[2]), "+f"((c)[3])             \
        : "r"((a)[0]), "r"((a)[1]), "r"((a)[2]), "r"((a)[3]),                \
          "r"((b)[0]), "r"((b)[1]))

#define LDM_X4(r, addr)                                                      \
    asm volatile(                                                            \
        "ldmatrix.sync.aligned.m8n8.x4.shared.b16 {%0,%1,%2,%3}, [%4];"      \
        : "=r"((r)[0]), "=r"((r)[1]), "=r"((r)[2]), "=r"((r)[3])             \
        : "r"(addr))

__device__ __forceinline__ uint32_t pack_bf16x2(float lo, float hi)
{
    uint32_t r;
    asm("cvt.rn.bf16x2.f32 %0, %1, %2;" : "=r"(r) : "f"(hi), "f"(lo));
    return r;
}

__device__ __forceinline__ void split2(float x, float y,
                                       uint32_t& hi, uint32_t& lo)
{
    hi = pack_bf16x2(x, y);
    float fx = __uint_as_float(hi << 16);
    float fy = __uint_as_float(hi & 0xFFFF0000u);
    lo = pack_bf16x2(x - fx, y - fy);
}

// plane-smem word index: [r][p] with 16B-granular XOR
#define PW(r, p) (((r) << 3) + ((p) ^ ((((r) >> 2) & 1) << 2)))

#define CP_COMMIT() asm volatile("cp.async.commit_group;" ::: "memory")
#define CP_WAIT1()  asm volatile("cp.async.wait_group 1;"  ::: "memory")

// ---------------------------------------------------------------------------
// Weight converter (whole L-stack per call, once per launch)
// ---------------------------------------------------------------------------
__global__ void conv_w_kernel(const float2* __restrict__ W,
                              uint32_t* __restrict__ Wh,
                              uint32_t* __restrict__ Wl, int npairs)
{
    int i = blockIdx.x * blockDim.x + threadIdx.x;
    if (i >= npairs) return;
    float2 w = W[i];
    uint32_t h, l;
    split2(w.x, w.y, h, l);
    Wh[i] = h;
    Wl[i] = l;
}

// ---------------------------------------------------------------------------
// x = q + pe (fp32 + planes) ; y planes only
// ---------------------------------------------------------------------------
__global__ void add_pos_kernel(const float4* __restrict__ q,
                               const float4* __restrict__ qa,
                               const float4* __restrict__ pe,
                               float4* __restrict__ x,
                               uint32_t* __restrict__ xh, uint32_t* __restrict__ xl,
                               uint32_t* __restrict__ yh, uint32_t* __restrict__ yl)
{
    int i = blockIdx.x * blockDim.x + threadIdx.x;
    if (i >= MROWS * D_ / 4) return;
    int pi = i % (S_ * D_ / 4);
    float4 p = pe[pi];
    float4 a = q[i];
    a.x += p.x; a.y += p.y; a.z += p.z; a.w += p.w;
    x[i] = a;
    uint32_t h, l;
    split2(a.x, a.y, h, l); xh[i * 2] = h;     xl[i * 2] = l;
    split2(a.z, a.w, h, l); xh[i * 2 + 1] = h; xl[i * 2 + 1] = l;
    float4 b = qa[i];
    b.x += p.x; b.y += p.y; b.z += p.z; b.w += p.w;
    split2(b.x, b.y, h, l); yh[i * 2] = h;     yl[i * 2] = l;
    split2(b.z, b.w, h, l); yh[i * 2 + 1] = h; yl[i * 2 + 1] = l;
}

// ---------------------------------------------------------------------------
// Plane-consuming tensor-core GEMM, cp.async x3 ring + ldmatrix fragments,
// A-fragment software pipeline across the mt loop.
// MODE 0: fp32 C out.  MODE 1: ReLU + planes out.  MODE 2: planes out.
// ---------------------------------------------------------------------------
template <int MODE>
__global__ void __launch_bounds__(256)
gemm_cp_kernel(const uint32_t* __restrict__ Ah, const uint32_t* __restrict__ Al,
               const uint32_t* __restrict__ Bh, const uint32_t* __restrict__ Bl,
               const float* __restrict__ bias,
               float* __restrict__ C,
               uint32_t* __restrict__ Ch, uint32_t* __restrict__ Cl,
               int M, int N, int K)
{
    __shared__ uint32_t sP[3][4][1024];   // [stage][Ah,Al,Bh,Bl][128r x 8p]

    const int tid  = threadIdx.x;
    const int lane = tid & 31;
    const int warp = tid >> 5;
    const int wm   = warp & 1;
    const int wn   = warp >> 1;
    const int lq   = lane & 3;
    const int lr   = lane >> 2;

    const int row0 = blockIdx.y * 128;
    const int col0 = blockIdx.x * 128;
    const int Kh   = K >> 1;
    const int nst  = K >> 4;

    const int pl = tid >> 6;
    const int t6 = tid & 63;
    const uint32_t* gsrc =
        (pl == 0 ? Ah : pl == 1 ? Al : pl == 2 ? Bh : Bl) +
        (size_t)(pl < 2 ? row0 : col0) * Kh;

    const int row_lane  = (lane & 7) + ((lane >> 3) & 1) * 8;
    const int half_lane = lane >> 4;

    uint32_t aoff[4], boff[2];
#pragma unroll
    for (int mt = 0; mt < 4; mt++)
        aoff[mt] = PW(wm * 64 + mt * 16 + row_lane, half_lane << 2) * 4;
#pragma unroll
    for (int j = 0; j < 2; j++) {
        int ntx = 2 * j + (lane >> 4);
        int hf  = (lane >> 3) & 1;
        boff[j] = PW(wn * 32 + ntx * 8 + (lane & 7), hf << 2) * 4;
    }

    const uint32_t sb0 = (uint32_t)__cvta_generic_to_shared(&sP[0][0][0]);

    float acc[4][4][4];
#pragma unroll
    for (int mt = 0; mt < 4; mt++)
#pragma unroll
        for (int nt = 0; nt < 4; nt++)
#pragma unroll
            for (int e = 0; e < 4; e++) acc[mt][nt][e] = 0.0f;

#define ISSUE_STAGE(kb, bi)                                                   \
    {                                                                         \
        _Pragma("unroll")                                                     \
        for (int c = 0; c < 4; c++) {                                         \
            int r = t6 * 2 + (c >> 1), qq = c & 1;                            \
            const uint32_t* g = gsrc + (size_t)r * Kh + (kb) * 8 + qq * 4;    \
            uint32_t word = r * 8 + ((qq ^ ((r >> 2) & 1)) << 2);             \
            uint32_t sa = (uint32_t)__cvta_generic_to_shared(                 \
                &sP[bi][pl][word]);                                           \
            asm volatile("cp.async.cg.shared.global [%0], [%1], 16;"          \
                         :: "r"(sa), "l"(g));                                 \
        }                                                                     \
    }

    ISSUE_STAGE(0, 0); CP_COMMIT();
    ISSUE_STAGE(1, 1); CP_COMMIT();

    for (int i = 0; i < nst; i++) {
        CP_WAIT1();
        __syncthreads();

        const uint32_t sbase = sb0 + (uint32_t)(i % 3) * 16384;

        uint32_t bhf[2][4], blf[2][4];
        LDM_X4(bhf[0], sbase + 8192  + boff[0]);
        LDM_X4(bhf[1], sbase + 8192  + boff[1]);
        LDM_X4(blf[0], sbase + 12288 + boff[0]);
        LDM_X4(blf[1], sbase + 12288 + boff[1]);

        uint32_t ahf[2][4], alf[2][4];
        LDM_X4(ahf[0], sbase +        aoff[0]);
        LDM_X4(alf[0], sbase + 4096 + aoff[0]);

#pragma unroll
        for (int mt = 0; mt < 4; mt++) {
            const int cb = mt & 1;
            if (mt < 3) {
                LDM_X4(ahf[cb ^ 1], sbase +        aoff[mt + 1]);
                LDM_X4(alf[cb ^ 1], sbase + 4096 + aoff[mt + 1]);
            }
#pragma unroll
            for (int nt = 0; nt < 4; nt++) {
                const uint32_t* bh2 = &bhf[nt >> 1][(nt & 1) * 2];
                const uint32_t* bl2 = &blf[nt >> 1][(nt & 1) * 2];
                MMA_BF16(acc[mt][nt], ahf[cb], bl2);   // small terms first
                MMA_BF16(acc[mt][nt], alf[cb], bh2);
                MMA_BF16(acc[mt][nt], ahf[cb], bh2);
            }
        }

        if (i + 2 < nst) ISSUE_STAGE(i + 2, (i + 2) % 3);
        CP_COMMIT();
    }
#undef ISSUE_STAGE

    // ---- epilogue ----
    const int Nh = N >> 1;
#pragma unroll
    for (int nt = 0; nt < 4; nt++) {
        int c  = col0 + wn * 32 + nt * 8 + 2 * lq;
        float bv0 = bias[c];
        float bv1 = bias[c + 1];
#pragma unroll
        for (int mt = 0; mt < 4; mt++) {
            int r = row0 + wm * 64 + mt * 16 + lr;
            float o00 = acc[mt][nt][0] + bv0;
            float o01 = acc[mt][nt][1] + bv1;
            float o10 = acc[mt][nt][2] + bv0;
            float o11 = acc[mt][nt][3] + bv1;
            if (MODE >= 1) {
                if (MODE == 1) {
                    o00 = fmaxf(o00, 0.0f); o01 = fmaxf(o01, 0.0f);
                    o10 = fmaxf(o10, 0.0f); o11 = fmaxf(o11, 0.0f);
                }
                uint32_t h, l;
                int pk = c >> 1;
                split2(o00, o01, h, l);
                Ch[(size_t)r * Nh + pk] = h;
                Cl[(size_t)r * Nh + pk] = l;
                split2(o10, o11, h, l);
                Ch[(size_t)(r + 8) * Nh + pk] = h;
                Cl[(size_t)(r + 8) * Nh + pk] = l;
            } else {
                *(float2*)&C[(size_t)r * N + c]       = make_float2(o00, o01);
                *(float2*)&C[(size_t)(r + 8) * N + c] = make_float2(o10, o11);
            }
        }
    }
}

// ---------------------------------------------------------------------------
// Tensor-core flash attention (split-bf16 x3), fully plane-fed.
// 128 threads / 4 warps, 64-query tile, __launch_bounds__(128,3) -> 3 CTA/SM.
// K staged by u32 transpose-copy; V staged by PRMT key-pair repack.
// ---------------------------------------------------------------------------
#define SWZ64(p, r) (((p) << 6) + ((r) ^ (((p) & 3) << 3)))

__global__ void __launch_bounds__(128, 3)
attn_tc_kernel(const uint32_t* __restrict__ kh,
               const uint32_t* __restrict__ kl,
               const uint32_t* __restrict__ vh,
               const uint32_t* __restrict__ vl,
               const float* __restrict__ fr,
               uint32_t* __restrict__ ctxh,
               uint32_t* __restrict__ ctxl)
{
    __shared__ uint32_t sKh[32 * 64], sKl[32 * 64];
    __shared__ uint32_t sVh[32 * 64], sVl[32 * 64];

    const int qt   = blockIdx.x;          // 0..7 (64-row tiles)
    const int h    = blockIdx.y;
    const int b    = blockIdx.z;
    const int q0   = qt * 64;
    const int tid  = threadIdx.x;
    const int warp = tid >> 5;            // 0..3
    const int lane = tid & 31;
    const int lr   = lane >> 2;
    const int lq   = lane & 3;

    const int r0g = q0 + warp * 16 + lr;
    const size_t phb = (size_t)(b * S_) * (D_ / 2) + h * (DK_ / 2); // plane base
    const int    PD  = D_ / 2;                                      // plane row stride

    // ---- Q fragments: direct plane loads ----
    uint32_t qh[4][4], ql[4][4];
#pragma unroll
    for (int ks = 0; ks < 4; ks++) {
        size_t p0 = phb + (size_t)r0g * PD + ks * 8;
        size_t p1 = phb + (size_t)(r0g + 8) * PD + ks * 8;
        qh[ks][0] = kh[p0 + lq];     ql[ks][0] = kl[p0 + lq];
        qh[ks][1] = kh[p1 + lq];     ql[ks][1] = kl[p1 + lq];
        qh[ks][2] = kh[p0 + 4 + lq]; ql[ks][2] = kl[p0 + 4 + lq];
        qh[ks][3] = kh[p1 + 4 + lq]; ql[ks][3] = kl[p1 + 4 + lq];
    }

    float m0 = -1e30f, m1 = -1e30f, l0 = 0.0f, l1 = 0.0f;
    float acc[8][4];
#pragma unroll
    for (int nt = 0; nt < 8; nt++)
#pragma unroll
        for (int e = 0; e < 4; e++) acc[nt][e] = 0.0f;

    const float rf0 = 0.125f * fr[b * S_ + r0g];
    const float rf1 = 0.125f * fr[b * S_ + r0g + 8];

    const int nkt = qt + 1;
    for (int kt = 0; kt < nkt; kt++) {
        const int t0 = kt * 64;
        __syncthreads();

        // ---- stage K tile: u32 transpose-copy from planes ----
        for (int t = tid; t < 512; t += 128) {
            int key = t >> 3;            // 0..63
            int p4  = (t & 7) << 2;      // 0,4,...,28
            size_t src = phb + (size_t)(t0 + key) * PD + p4;
            uint4 wh = *(const uint4*)&kh[src];
            sKh[SWZ64(p4 + 0, key)] = wh.x;
            sKh[SWZ64(p4 + 1, key)] = wh.y;
            sKh[SWZ64(p4 + 2, key)] = wh.z;
            sKh[SWZ64(p4 + 3, key)] = wh.w;
            uint4 wl = *(const uint4*)&kl[src];
            sKl[SWZ64(p4 + 0, key)] = wl.x;
            sKl[SWZ64(p4 + 1, key)] = wl.y;
            sKl[SWZ64(p4 + 2, key)] = wl.z;
            sKl[SWZ64(p4 + 3, key)] = wl.w;
        }
        // ---- stage V tile: PRMT key-pair repack from planes ----
        // plane word [key][dkpair] = (dk even lo, dk odd hi);
        // smem word (kp, c) = (V[2kp][c] lo, V[2kp+1][c] hi)
        for (int t = tid; t < 512; t += 128) {
            int kp = t >> 4;             // 0..31
            int c4 = (t & 15) << 2;      // 0,4,...,60
            size_t s0 = phb + (size_t)(t0 + 2 * kp)     * PD + (c4 >> 1);
            size_t s1 = phb + (size_t)(t0 + 2 * kp + 1) * PD + (c4 >> 1);
            uint2 a = *(const uint2*)&vh[s0];
            uint2 c = *(const uint2*)&vh[s1];
            sVh[SWZ64(kp, c4 + 0)] = __byte_perm(a.x, c.x, 0x5410);
            sVh[SWZ64(kp, c4 + 1)] = __byte_perm(a.x, c.x, 0x7632);
            sVh[SWZ64(kp, c4 + 2)] = __byte_perm(a.y, c.y, 0x5410);
            sVh[SWZ64(kp, c4 + 3)] = __byte_perm(a.y, c.y, 0x7632);
            uint2 d = *(const uint2*)&vl[s0];
            uint2 e = *(const uint2*)&vl[s1];
            sVl[SWZ64(kp, c4 + 0)] = __byte_perm(d.x, e.x, 0x5410);
            sVl[SWZ64(kp, c4 + 1)] = __byte_perm(d.x, e.x, 0x7632);
            sVl[SWZ64(kp, c4 + 2)] = __byte_perm(d.y, e.y, 0x5410);
            sVl[SWZ64(kp, c4 + 3)] = __byte_perm(d.y, e.y, 0x7632);
        }
        __syncthreads();

        float sc[8][4];
#pragma unroll
        for (int nt = 0; nt < 8; nt++)
#pragma unroll
            for (int e = 0; e < 4; e++) sc[nt][e] = 0.0f;

#pragma unroll
        for (int ks = 0; ks < 4; ks++) {
            int pa = ks * 8 + lq, pb = pa + 4;
#pragma unroll
            for (int nt = 0; nt < 8; nt++) {
                int n = nt * 8 + lr;
                uint32_t bh[2] = { sKh[SWZ64(pa, n)], sKh[SWZ64(pb, n)] };
                uint32_t bl[2] = { sKl[SWZ64(pa, n)], sKl[SWZ64(pb, n)] };
                MMA_BF16(sc[nt], qh[ks], bl);
                MMA_BF16(sc[nt], ql[ks], bh);
                MMA_BF16(sc[nt], qh[ks], bh);
            }
        }

        const bool needmask = (t0 + 63 >= q0 + warp * 16);
#pragma unroll
        for (int nt = 0; nt < 8; nt++) {
            sc[nt][0] *= rf0; sc[nt][1] *= rf0;
            sc[nt][2] *= rf1; sc[nt][3] *= rf1;
            if (needmask) {
                int c0 = t0 + nt * 8 + 2 * lq;
                if (c0     >= r0g)     sc[nt][0] = -1e30f;
                if (c0 + 1 >= r0g)     sc[nt][1] = -1e30f;
                if (c0     >= r0g + 8) sc[nt][2] = -1e30f;
                if (c0 + 1 >= r0g + 8) sc[nt][3] = -1e30f;
            }
        }

        float mt0 = -1e30f, mt1 = -1e30f;
#pragma unroll
        for (int nt = 0; nt < 8; nt++) {
            mt0 = fmaxf(mt0, fmaxf(sc[nt][0], sc[nt][1]));
            mt1 = fmaxf(mt1, fmaxf(sc[nt][2], sc[nt][3]));
        }
        mt0 = fmaxf(mt0, __shfl_xor_sync(0xffffffffu, mt0, 1));
        mt0 = fmaxf(mt0, __shfl_xor_sync(0xffffffffu, mt0, 2));
        mt1 = fmaxf(mt1, __shfl_xor_sync(0xffffffffu, mt1, 1));
        mt1 = fmaxf(mt1, __shfl_xor_sync(0xffffffffu, mt1, 2));

        float mn0 = fmaxf(m0, mt0), mn1 = fmaxf(m1, mt1);
        float al0 = __expf(m0 - mn0), al1 = __expf(m1 - mn1);
        m0 = mn0; m1 = mn1;

        float rs0 = 0.0f, rs1 = 0.0f;
#pragma unroll
        for (int nt = 0; nt < 8; nt++) {
            sc[nt][0] = __expf(sc[nt][0] - mn0);
            sc[nt][1] = __expf(sc[nt][1] - mn0);
            sc[nt][2] = __expf(sc[nt][2] - mn1);
            sc[nt][3] = __expf(sc[nt][3] - mn1);
            rs0 += sc[nt][0] + sc[nt][1];
            rs1 += sc[nt][2] + sc[nt][3];
        }
        rs0 += __shfl_xor_sync(0xffffffffu, rs0, 1);
        rs0 += __shfl_xor_sync(0xffffffffu, rs0, 2);
        rs1 += __shfl_xor_sync(0xffffffffu, rs1, 1);
        rs1 += __shfl_xor_sync(0xffffffffu, rs1, 2);
        l0 = l0 * al0 + rs0;
        l1 = l1 * al1 + rs1;

#pragma unroll
        for (int nt = 0; nt < 8; nt++) {
            acc[nt][0] *= al0; acc[nt][1] *= al0;
            acc[nt][2] *= al1; acc[nt][3] *= al1;
        }

#pragma unroll
        for (int ks = 0; ks < 4; ks++) {
            uint32_t ph[4], pl2[4];
            split2(sc[2 * ks][0],     sc[2 * ks][1],     ph[0], pl2[0]);
            split2(sc[2 * ks][2],     sc[2 * ks][3],     ph[1], pl2[1]);
            split2(sc[2 * ks + 1][0], sc[2 * ks + 1][1], ph[2], pl2[2]);
            split2(sc[2 * ks + 1][2], sc[2 * ks + 1][3], ph[3], pl2[3]);
            int pa = ks * 8 + lq, pb = pa + 4;
#pragma unroll
            for (int nt = 0; nt < 8; nt++) {
                int n = nt * 8 + lr;
                uint32_t vhf[2] = { sVh[SWZ64(pa, n)], sVh[SWZ64(pb, n)] };
                uint32_t vlf[2] = { sVl[SWZ64(pa, n)], sVl[SWZ64(pb, n)] };
                MMA_BF16(acc[nt], ph,  vlf);
                MMA_BF16(acc[nt], pl2, vhf);
                MMA_BF16(acc[nt], ph,  vhf);
            }
        }
    }

    const float inv0 = 1.0f / l0;
    const float inv1 = 1.0f / l1;
    const size_t pb0 = phb + (size_t)r0g * PD;
    const size_t pb1 = phb + (size_t)(r0g + 8) * PD;
#pragma unroll
    for (int nt = 0; nt < 8; nt++) {
        int c = nt * 8 + 2 * lq;
        float o00 = acc[nt][0] * inv0, o01 = acc[nt][1] * inv0;
        float o10 = acc[nt][2] * inv1, o11 = acc[nt][3] * inv1;
        if (r0g == 0) { o00 = 0.0f; o01 = 0.0f; }
        uint32_t th, tl;
        split2(o00, o01, th, tl);
        ctxh[pb0 + (c >> 1)] = th; ctxl[pb0 + (c >> 1)] = tl;
        split2(o10, o11, th, tl);
        ctxh[pb1 + (c >> 1)] = th; ctxl[pb1 + (c >> 1)] = tl;
    }
}

// ---------------------------------------------------------------------------
// xout = LayerNorm(xin + res) * g + beta   (fp32 + planes)
// ---------------------------------------------------------------------------
__global__ void __launch_bounds__(128)
add_ln_kernel(const float* __restrict__ xin,
              const float* __restrict__ res,
              const float* __restrict__ g,
              const float* __restrict__ beta,
              float* __restrict__ xout,
              uint32_t* __restrict__ xh, uint32_t* __restrict__ xl)
{
    const int row = blockIdx.x;
    const int tid = threadIdx.x;

    float4 a = ((const float4*)(xin + (size_t)row * D_))[tid];
    float4 b = ((const float4*)(res + (size_t)row * D_))[tid];
    float v0 = a.x + b.x, v1 = a.y + b.y, v2 = a.z + b.z, v3 = a.w + b.w;

    float s  = v0 + v1 + v2 + v3;
    float sq = v0 * v0 + v1 * v1 + v2 * v2 + v3 * v3;
#pragma unroll
    for (int off = 16; off >= 1; off >>= 1) {
        s  += __shfl_xor_sync(0xffffffffu, s,  off);
        sq += __shfl_xor_sync(0xffffffffu, sq, off);
    }
    __shared__ float ss[4], ssq[4];
    int w = tid >> 5, lane = tid & 31;
    if (lane == 0) { ss[w] = s; ssq[w] = sq; }
    __syncthreads();
    s  = ss[0]  + ss[1]  + ss[2]  + ss[3];
    sq = ssq[0] + ssq[1] + ssq[2] + ssq[3];

    const float mu   = s * (1.0f / (float)D_);
    const float var  = sq * (1.0f / (float)D_) - mu * mu;
    const float rstd = rsqrtf(var + 1e-5f);

    float4 gg = ((const float4*)g)[tid];
    float4 bb = ((const float4*)beta)[tid];
    float4 o;
    o.x = (v0 - mu) * rstd * gg.x + bb.x;
    o.y = (v1 - mu) * rstd * gg.y + bb.y;
    o.z = (v2 - mu) * rstd * gg.z + bb.z;
    o.w = (v3 - mu) * rstd * gg.w + bb.w;
    ((float4*)(xout + (size_t)row * D_))[tid] = o;

    uint32_t h, l;
    size_t pidx = (size_t)row * (D_ / 2) + tid * 2;
    split2(o.x, o.y, h, l); xh[pidx] = h;     xl[pidx] = l;
    split2(o.z, o.w, h, l); xh[pidx + 1] = h; xl[pidx + 1] = l;
}

// ---------------------------------------------------------------------------
// Orchestration
// ---------------------------------------------------------------------------
extern "C" void kernel_launch(void* const* d_in, const int* in_sizes, int n_in,
                              void* d_out, int out_size)
{
    const float* q   = (const float*)d_in[0];
    const float* qa  = (const float*)d_in[1];
    const float* fr  = (const float*)d_in[2];
    const float* pe  = (const float*)d_in[3];
    const float* Wk  = (const float*)d_in[4];
    const float* bk  = (const float*)d_in[5];
    const float* Wv  = (const float*)d_in[6];
    const float* bv  = (const float*)d_in[7];
    const float* Wo  = (const float*)d_in[8];
    const float* bo  = (const float*)d_in[9];
    const float* W1  = (const float*)d_in[10];
    const float* b1  = (const float*)d_in[11];
    const float* W2  = (const float*)d_in[12];
    const float* b2  = (const float*)d_in[13];
    const float* g1  = (const float*)d_in[14];
    const float* be1 = (const float*)d_in[15];
    const float* g2  = (const float*)d_in[16];
    const float* be2 = (const float*)d_in[17];
    float* out = (float*)d_out;

    float *x, *ob;
    uint32_t *xh, *xl, *yh, *yl, *kh, *kl, *vh, *vl, *ch, *cl, *hh, *hl, *wAh, *wAl;
    cudaGetSymbolAddress((void**)&x,   g_x);
    cudaGetSymbolAddress((void**)&ob,  g_o);
    cudaGetSymbolAddress((void**)&xh,  g_xh);
    cudaGetSymbolAddress((void**)&xl,  g_xl);
    cudaGetSymbolAddress((void**)&yh,  g_yh);
    cudaGetSymbolAddress((void**)&yl,  g_yl);
    cudaGetSymbolAddress((void**)&kh,  g_kh);
    cudaGetSymbolAddress((void**)&kl,  g_kl);
    cudaGetSymbolAddress((void**)&vh,  g_vh);
    cudaGetSymbolAddress((void**)&vl,  g_vl);
    cudaGetSymbolAddress((void**)&ch,  g_ch);
    cudaGetSymbolAddress((void**)&cl,  g_cl);
    cudaGetSymbolAddress((void**)&hh,  g_hh);
    cudaGetSymbolAddress((void**)&hl,  g_hl);
    cudaGetSymbolAddress((void**)&wAh, g_wAh);
    cudaGetSymbolAddress((void**)&wAl, g_wAl);

    conv_w_kernel<<<LDDP / 256, 256>>>((const float2*)Wk, wAh,            wAl,            LDDP);
    conv_w_kernel<<<LDDP / 256, 256>>>((const float2*)Wv, wAh + LDDP,     wAl + LDDP,     LDDP);
    conv_w_kernel<<<LDDP / 256, 256>>>((const float2*)Wo, wAh + 2 * LDDP, wAl + 2 * LDDP, LDDP);
    conv_w_kernel<<<LFDP / 256, 256>>>((const float2*)W1, wAh + 3 * LDDP, wAl + 3 * LDDP, LFDP);
    conv_w_kernel<<<LFDP / 256, 256>>>((const float2*)W2, wAh + 3 * LDDP + LFDP,
                                                          wAl + 3 * LDDP + LFDP, LFDP);

    {
        int n4 = MROWS * D_ / 4;
        add_pos_kernel<<<(n4 + 255) / 256, 256>>>(
            (const float4*)q, (const float4*)qa, (const float4*)pe,
            (float4*)x, xh, xl, yh, yl);
    }

    const dim3 gD(D_ / 128, MROWS / 128);   // (4, 128)
    const dim3 gF(F_ / 128, MROWS / 128);   // (16, 128)
    const dim3 gA(S_ / 64, H_, B_);         // (8, 8, 32)
    const int  pDD = D_ * D_ / 2;
    const int  pFD = F_ * D_ / 2;

    for (int l = 0; l < L_; l++) {
        const uint32_t* kWh = wAh + (size_t)l * pDD;
        const uint32_t* kWl = wAl + (size_t)l * pDD;
        const uint32_t* vWh = wAh + LDDP + (size_t)l * pDD;
        const uint32_t* vWl = wAl + LDDP + (size_t)l * pDD;
        const uint32_t* oWh = wAh + 2 * LDDP + (size_t)l * pDD;
        const uint32_t* oWl = wAl + 2 * LDDP + (size_t)l * pDD;
        const uint32_t* w1h = wAh + 3 * LDDP + (size_t)l * pFD;
        const uint32_t* w1l = wAl + 3 * LDDP + (size_t)l * pFD;
        const uint32_t* w2h = wAh + 3 * LDDP + LFDP + (size_t)l * pFD;
        const uint32_t* w2l = wAl + 3 * LDDP + LFDP + (size_t)l * pFD;

        gemm_cp_kernel<2><<<gD, 256>>>(xh, xl, kWh, kWl, bk + l * D_,
                                       nullptr, kh, kl, MROWS, D_, D_);
        gemm_cp_kernel<2><<<gD, 256>>>(yh, yl, vWh, vWl, bv + l * D_,
                                       nullptr, vh, vl, MROWS, D_, D_);
        attn_tc_kernel<<<gA, 128>>>(kh, kl, vh, vl, fr, ch, cl);
        gemm_cp_kernel<0><<<gD, 256>>>(ch, cl, oWh, oWl, bo + l * D_,
                                       ob, nullptr, nullptr, MROWS, D_, D_);
        add_ln_kernel<<<MROWS, 128>>>(x, ob, g1 + l * D_, be1 + l * D_, x, xh, xl);
        gemm_cp_kernel<1><<<gF, 256>>>(xh, xl, w1h, w1l, b1 + l * F_,
                                       nullptr, hh, hl, MROWS, F_, D_);
        gemm_cp_kernel<0><<<gD, 256>>>(hh, hl, w2h, w2l, b2 + l * D_,
                                       ob, nullptr, nullptr, MROWS, D_, F_);
        add_ln_kernel<<<MROWS, 128>>>(x, ob, g2 + l * D_, be2 + l * D_,
                                      (l == L_ - 1) ? out : x, xh, xl);
    }
}

// round 17
// speedup vs baseline: 1.1159x; 1.1159x over previous
#include <cuda_runtime.h>
#include <cstdint>
#include <cstddef>

// ---------------------------------------------------------------------------
// Problem constants
// ---------------------------------------------------------------------------
#define B_   32
#define S_   512
#define D_   512
#define H_   8
#define L_   4
#define F_   2048
#define DK_  64
#define MROWS (B_ * S_)            // 16384 token rows

#define LDDP (L_ * D_ * D_ / 2)    // pairs in one L-stack of DxD weights
#define LFDP (L_ * F_ * D_ / 2)    // pairs in one L-stack of FxD weights
#define WPAIRS (3 * LDDP + 2 * LFDP)

// ---------------------------------------------------------------------------
// Scratch (static device arrays: no allocations allowed)
// ---------------------------------------------------------------------------
__device__ float g_x  [MROWS * D_];   // residual stream fp32
__device__ float g_kq [MROWS * D_];   // kq projection fp32
__device__ float g_v  [MROWS * D_];   // v projection fp32
__device__ float g_o  [MROWS * D_];   // gemm outputs pre-LN
// split-bf16 planes, layout [row][kpair] u32 (bf16x2, even k in low half):
__device__ uint32_t g_xh[MROWS * (D_/2)], g_xl[MROWS * (D_/2)];
__device__ uint32_t g_yh[MROWS * (D_/2)], g_yl[MROWS * (D_/2)];
__device__ uint32_t g_ch[MROWS * (D_/2)], g_cl[MROWS * (D_/2)];   // ctx planes
__device__ uint32_t g_hh[MROWS * (F_/2)], g_hl[MROWS * (F_/2)];   // ffn hidden
__device__ uint32_t g_wAh[WPAIRS], g_wAl[WPAIRS];                 // weights

// ---------------------------------------------------------------------------
// Helpers
// ---------------------------------------------------------------------------
#define MMA_BF16(c, a, b)                                                    \
    asm volatile(                                                            \
        "mma.sync.aligned.m16n8k16.row.col.f32.bf16.bf16.f32 "               \
        "{%0,%1,%2,%3},{%4,%5,%6,%7},{%8,%9},{%0,%1,%2,%3};"                 \
        : "+f"((c)[0]), "+f"((c)[1]), "+f"((c)[2]), "+f"((c)[3])             \
        : "r"((a)[0]), "r"((a)[1]), "r"((a)[2]), "r"((a)[3]),                \
          "r"((b)[0]), "r"((b)[1]))

#define LDM_X4(r, addr)                                                      \
    asm volatile(                                                            \
        "ldmatrix.sync.aligned.m8n8.x4.shared.b16 {%0,%1,%2,%3}, [%4];"      \
        : "=r"((r)[0]), "=r"((r)[1]), "=r"((r)[2]), "=r"((r)[3])             \
        : "r"(addr))

__device__ __forceinline__ uint32_t pack_bf16x2(float lo, float hi)
{
    uint32_t r;
    asm("cvt.rn.bf16x2.f32 %0, %1, %2;" : "=r"(r) : "f"(hi), "f"(lo));
    return r;
}

__device__ __forceinline__ void split2(float x, float y,
                                       uint32_t& hi, uint32_t& lo)
{
    hi = pack_bf16x2(x, y);
    float fx = __uint_as_float(hi << 16);
    float fy = __uint_as_float(hi & 0xFFFF0000u);
    lo = pack_bf16x2(x - fx, y - fy);
}

// plane-smem word index: [r][p] with 16B-granular XOR
#define PW(r, p) (((r) << 3) + ((p) ^ ((((r) >> 2) & 1) << 2)))

#define CP_COMMIT() asm volatile("cp.async.commit_group;" ::: "memory")
#define CP_WAIT1()  asm volatile("cp.async.wait_group 1;"  ::: "memory")

// ---------------------------------------------------------------------------
// Weight converter (whole L-stack per call, once per launch)
// ---------------------------------------------------------------------------
__global__ void conv_w_kernel(const float2* __restrict__ W,
                              uint32_t* __restrict__ Wh,
                              uint32_t* __restrict__ Wl, int npairs)
{
    int i = blockIdx.x * blockDim.x + threadIdx.x;
    if (i >= npairs) return;
    float2 w = W[i];
    uint32_t h, l;
    split2(w.x, w.y, h, l);
    Wh[i] = h;
    Wl[i] = l;
}

// ---------------------------------------------------------------------------
// x = q + pe (fp32 + planes) ; y planes only
// ---------------------------------------------------------------------------
__global__ void add_pos_kernel(const float4* __restrict__ q,
                               const float4* __restrict__ qa,
                               const float4* __restrict__ pe,
                               float4* __restrict__ x,
                               uint32_t* __restrict__ xh, uint32_t* __restrict__ xl,
                               uint32_t* __restrict__ yh, uint32_t* __restrict__ yl)
{
    int i = blockIdx.x * blockDim.x + threadIdx.x;
    if (i >= MROWS * D_ / 4) return;
    int pi = i % (S_ * D_ / 4);
    float4 p = pe[pi];
    float4 a = q[i];
    a.x += p.x; a.y += p.y; a.z += p.z; a.w += p.w;
    x[i] = a;
    uint32_t h, l;
    split2(a.x, a.y, h, l); xh[i * 2] = h;     xl[i * 2] = l;
    split2(a.z, a.w, h, l); xh[i * 2 + 1] = h; xl[i * 2 + 1] = l;
    float4 b = qa[i];
    b.x += p.x; b.y += p.y; b.z += p.z; b.w += p.w;
    split2(b.x, b.y, h, l); yh[i * 2] = h;     yl[i * 2] = l;
    split2(b.z, b.w, h, l); yh[i * 2 + 1] = h; yl[i * 2 + 1] = l;
}

// ---------------------------------------------------------------------------
// GEMM core (device inline): plane-consuming, cp.async x3 + ldmatrix.
// Computes one 128x128 C tile; epilogue per MODE.
// ---------------------------------------------------------------------------
template <int MODE>
__device__ __forceinline__ void gemm_body(
    const uint32_t* __restrict__ Ah, const uint32_t* __restrict__ Al,
    const uint32_t* __restrict__ Bh, const uint32_t* __restrict__ Bl,
    const float* __restrict__ bias,
    float* __restrict__ C,
    uint32_t* __restrict__ Ch, uint32_t* __restrict__ Cl,
    int N, int K, uint32_t* sPraw)
{
    // sPraw: [3][4][1024]
    const int tid  = threadIdx.x;
    const int lane = tid & 31;
    const int warp = tid >> 5;
    const int wm   = warp & 1;
    const int wn   = warp >> 1;
    const int lq   = lane & 3;
    const int lr   = lane >> 2;

    const int row0 = blockIdx.y * 128;
    const int col0 = blockIdx.x * 128;
    const int Kh   = K >> 1;
    const int nst  = K >> 4;

    const int pl = tid >> 6;
    const int t6 = tid & 63;
    const uint32_t* gsrc =
        (pl == 0 ? Ah : pl == 1 ? Al : pl == 2 ? Bh : Bl) +
        (size_t)(pl < 2 ? row0 : col0) * Kh;

    const int row_lane  = (lane & 7) + ((lane >> 3) & 1) * 8;
    const int half_lane = lane >> 4;

    uint32_t aoff[4], boff[2];
#pragma unroll
    for (int mt = 0; mt < 4; mt++)
        aoff[mt] = PW(wm * 64 + mt * 16 + row_lane, half_lane << 2) * 4;
#pragma unroll
    for (int j = 0; j < 2; j++) {
        int ntx = 2 * j + (lane >> 4);
        int hf  = (lane >> 3) & 1;
        boff[j] = PW(wn * 32 + ntx * 8 + (lane & 7), hf << 2) * 4;
    }

    const uint32_t sb0 = (uint32_t)__cvta_generic_to_shared(sPraw);

    float acc[4][4][4];
#pragma unroll
    for (int mt = 0; mt < 4; mt++)
#pragma unroll
        for (int nt = 0; nt < 4; nt++)
#pragma unroll
            for (int e = 0; e < 4; e++) acc[mt][nt][e] = 0.0f;

#define ISSUE_STAGE(kb, bi)                                                   \
    {                                                                         \
        _Pragma("unroll")                                                     \
        for (int c = 0; c < 4; c++) {                                         \
            int r = t6 * 2 + (c >> 1), qq = c & 1;                            \
            const uint32_t* g = gsrc + (size_t)r * Kh + (kb) * 8 + qq * 4;    \
            uint32_t word = r * 8 + ((qq ^ ((r >> 2) & 1)) << 2);             \
            uint32_t sa = sb0 + ((bi) * 4096 + pl * 1024 + word) * 4;         \
            asm volatile("cp.async.cg.shared.global [%0], [%1], 16;"          \
                         :: "r"(sa), "l"(g));                                 \
        }                                                                     \
    }

    ISSUE_STAGE(0, 0); CP_COMMIT();
    ISSUE_STAGE(1, 1); CP_COMMIT();

    for (int i = 0; i < nst; i++) {
        CP_WAIT1();
        __syncthreads();

        const uint32_t sbase = sb0 + (uint32_t)(i % 3) * 16384;

        uint32_t bhf[2][4], blf[2][4];
        LDM_X4(bhf[0], sbase + 8192  + boff[0]);
        LDM_X4(bhf[1], sbase + 8192  + boff[1]);
        LDM_X4(blf[0], sbase + 12288 + boff[0]);
        LDM_X4(blf[1], sbase + 12288 + boff[1]);

#pragma unroll
        for (int mt = 0; mt < 4; mt++) {
            uint32_t ahf[4], alf[4];
            LDM_X4(ahf, sbase +        aoff[mt]);
            LDM_X4(alf, sbase + 4096 + aoff[mt]);
#pragma unroll
            for (int nt = 0; nt < 4; nt++) {
                const uint32_t* bh2 = &bhf[nt >> 1][(nt & 1) * 2];
                const uint32_t* bl2 = &blf[nt >> 1][(nt & 1) * 2];
                MMA_BF16(acc[mt][nt], ahf, bl2);   // small terms first
                MMA_BF16(acc[mt][nt], alf, bh2);
                MMA_BF16(acc[mt][nt], ahf, bh2);
            }
        }

        if (i + 2 < nst) ISSUE_STAGE(i + 2, (i + 2) % 3);
        CP_COMMIT();
    }
#undef ISSUE_STAGE

    // ---- epilogue ----
    const int Nh = N >> 1;
#pragma unroll
    for (int nt = 0; nt < 4; nt++) {
        int c  = col0 + wn * 32 + nt * 8 + 2 * lq;
        float bv0 = bias[c];
        float bv1 = bias[c + 1];
#pragma unroll
        for (int mt = 0; mt < 4; mt++) {
            int r = row0 + wm * 64 + mt * 16 + lr;
            float o00 = acc[mt][nt][0] + bv0;
            float o01 = acc[mt][nt][1] + bv1;
            float o10 = acc[mt][nt][2] + bv0;
            float o11 = acc[mt][nt][3] + bv1;
            if (MODE >= 1) {
                if (MODE == 1) {
                    o00 = fmaxf(o00, 0.0f); o01 = fmaxf(o01, 0.0f);
                    o10 = fmaxf(o10, 0.0f); o11 = fmaxf(o11, 0.0f);
                }
                uint32_t h, l;
                int pk = c >> 1;
                split2(o00, o01, h, l);
                Ch[(size_t)r * Nh + pk] = h;
                Cl[(size_t)r * Nh + pk] = l;
                split2(o10, o11, h, l);
                Ch[(size_t)(r + 8) * Nh + pk] = h;
                Cl[(size_t)(r + 8) * Nh + pk] = l;
            } else {
                *(float2*)&C[(size_t)r * N + c]       = make_float2(o00, o01);
                *(float2*)&C[(size_t)(r + 8) * N + c] = make_float2(o10, o11);
            }
        }
    }
}

template <int MODE>
__global__ void __launch_bounds__(256)
gemm_cp_kernel(const uint32_t* __restrict__ Ah, const uint32_t* __restrict__ Al,
               const uint32_t* __restrict__ Bh, const uint32_t* __restrict__ Bl,
               const float* __restrict__ bias,
               float* __restrict__ C,
               uint32_t* __restrict__ Ch, uint32_t* __restrict__ Cl,
               int M, int N, int K)
{
    __shared__ uint32_t sP[3 * 4 * 1024];
    gemm_body<MODE>(Ah, Al, Bh, Bl, bias, C, Ch, Cl, N, K, sP);
}

// Dual GEMM (MODE 0): z=0 computes C0 = A0 @ B0^T + b0; z=1 likewise.
// Merges the independent kq/v projections into one launch (wave packing).
__global__ void __launch_bounds__(256)
gemm_cp_dual_kernel(const uint32_t* __restrict__ Ah0, const uint32_t* __restrict__ Al0,
                    const uint32_t* __restrict__ Bh0, const uint32_t* __restrict__ Bl0,
                    const float* __restrict__ bias0, float* __restrict__ C0,
                    const uint32_t* __restrict__ Ah1, const uint32_t* __restrict__ Al1,
                    const uint32_t* __restrict__ Bh1, const uint32_t* __restrict__ Bl1,
                    const float* __restrict__ bias1, float* __restrict__ C1,
                    int N, int K)
{
    __shared__ uint32_t sP[3 * 4 * 1024];
    if (blockIdx.z == 0)
        gemm_body<0>(Ah0, Al0, Bh0, Bl0, bias0, C0, nullptr, nullptr, N, K, sP);
    else
        gemm_body<0>(Ah1, Al1, Bh1, Bl1, bias1, C1, nullptr, nullptr, N, K, sP);
}

// ---------------------------------------------------------------------------
// Tensor-core flash attention (split-bf16 x3): fp32 kq/v in, ctx planes out.
// 256 threads / 8 warps, 128-query tile. (Best-measured configuration.)
// ---------------------------------------------------------------------------
#define SWZ64(p, r) (((p) << 6) + ((r) ^ (((p) & 3) << 3)))

__global__ void __launch_bounds__(256)
attn_tc_kernel(const float* __restrict__ kq,
               const float* __restrict__ v,
               const float* __restrict__ fr,
               uint32_t* __restrict__ ctxh,
               uint32_t* __restrict__ ctxl)
{
    __shared__ uint32_t sKh[32 * 64], sKl[32 * 64];
    __shared__ uint32_t sVh[32 * 64], sVl[32 * 64];

    const int qt   = blockIdx.x;
    const int h    = blockIdx.y;
    const int b    = blockIdx.z;
    const int q0   = qt * 128;
    const int tid  = threadIdx.x;
    const int warp = tid >> 5;
    const int lane = tid & 31;
    const int lr   = lane >> 2;
    const int lq   = lane & 3;

    const int r0g = q0 + warp * 16 + lr;
    const size_t hb = (size_t)(b * S_) * D_ + h * DK_;

    uint32_t qh[4][4], ql[4][4];
#pragma unroll
    for (int ks = 0; ks < 4; ks++) {
#pragma unroll
        for (int half = 0; half < 2; half++) {
            int dk = ks * 16 + half * 8 + 2 * lq;
            float2 v0 = *(const float2*)&kq[hb + (size_t)r0g * D_ + dk];
            float2 v1 = *(const float2*)&kq[hb + (size_t)(r0g + 8) * D_ + dk];
            uint32_t th, tl;
            split2(v0.x, v0.y, th, tl);
            qh[ks][half * 2 + 0] = th; ql[ks][half * 2 + 0] = tl;
            split2(v1.x, v1.y, th, tl);
            qh[ks][half * 2 + 1] = th; ql[ks][half * 2 + 1] = tl;
        }
    }

    float m0 = -1e30f, m1 = -1e30f, l0 = 0.0f, l1 = 0.0f;
    float acc[8][4];
#pragma unroll
    for (int nt = 0; nt < 8; nt++)
#pragma unroll
        for (int e = 0; e < 4; e++) acc[nt][e] = 0.0f;

    const float rf0 = 0.125f * fr[b * S_ + r0g];
    const float rf1 = 0.125f * fr[b * S_ + r0g + 8];

    const int nkt = 2 * qt + 2;
    for (int kt = 0; kt < nkt; kt++) {
        const int t0 = kt * 64;
        __syncthreads();

        for (int t = tid; t < 1024; t += 256) {
            int key = t >> 4;
            int c4  = (t & 15) << 2;
            float4 kv = *(const float4*)&kq[hb + (size_t)(t0 + key) * D_ + c4];
            uint32_t h01, l01, h23, l23;
            split2(kv.x, kv.y, h01, l01);
            split2(kv.z, kv.w, h23, l23);
            int p = c4 >> 1;
            sKh[SWZ64(p, key)]     = h01;
            sKl[SWZ64(p, key)]     = l01;
            sKh[SWZ64(p + 1, key)] = h23;
            sKl[SWZ64(p + 1, key)] = l23;
        }
        for (int t = tid; t < 512; t += 256) {
            int kp = t >> 4;
            int c4 = (t & 15) << 2;
            const float* vb0 = &v[hb + (size_t)(t0 + 2 * kp) * D_ + c4];
            float4 a0 = *(const float4*)vb0;
            float4 a1 = *(const float4*)(vb0 + D_);
            uint32_t th, tl;
            split2(a0.x, a1.x, th, tl);
            sVh[SWZ64(kp, c4 + 0)] = th; sVl[SWZ64(kp, c4 + 0)] = tl;
            split2(a0.y, a1.y, th, tl);
            sVh[SWZ64(kp, c4 + 1)] = th; sVl[SWZ64(kp, c4 + 1)] = tl;
            split2(a0.z, a1.z, th, tl);
            sVh[SWZ64(kp, c4 + 2)] = th; sVl[SWZ64(kp, c4 + 2)] = tl;
            split2(a0.w, a1.w, th, tl);
            sVh[SWZ64(kp, c4 + 3)] = th; sVl[SWZ64(kp, c4 + 3)] = tl;
        }
        __syncthreads();

        float sc[8][4];
#pragma unroll
        for (int nt = 0; nt < 8; nt++)
#pragma unroll
            for (int e = 0; e < 4; e++) sc[nt][e] = 0.0f;

#pragma unroll
        for (int ks = 0; ks < 4; ks++) {
            int pa = ks * 8 + lq, pb = pa + 4;
#pragma unroll
            for (int nt = 0; nt < 8; nt++) {
                int n = nt * 8 + lr;
                uint32_t bh[2] = { sKh[SWZ64(pa, n)], sKh[SWZ64(pb, n)] };
                uint32_t bl[2] = { sKl[SWZ64(pa, n)], sKl[SWZ64(pb, n)] };
                MMA_BF16(sc[nt], qh[ks], bl);
                MMA_BF16(sc[nt], ql[ks], bh);
                MMA_BF16(sc[nt], qh[ks], bh);
            }
        }

        const bool needmask = (t0 + 63 >= q0 + warp * 16);
#pragma unroll
        for (int nt = 0; nt < 8; nt++) {
            sc[nt][0] *= rf0; sc[nt][1] *= rf0;
            sc[nt][2] *= rf1; sc[nt][3] *= rf1;
            if (needmask) {
                int c0 = t0 + nt * 8 + 2 * lq;
                if (c0     >= r0g)     sc[nt][0] = -1e30f;
                if (c0 + 1 >= r0g)     sc[nt][1] = -1e30f;
                if (c0     >= r0g + 8) sc[nt][2] = -1e30f;
                if (c0 + 1 >= r0g + 8) sc[nt][3] = -1e30f;
            }
        }

        float mt0 = -1e30f, mt1 = -1e30f;
#pragma unroll
        for (int nt = 0; nt < 8; nt++) {
            mt0 = fmaxf(mt0, fmaxf(sc[nt][0], sc[nt][1]));
            mt1 = fmaxf(mt1, fmaxf(sc[nt][2], sc[nt][3]));
        }
        mt0 = fmaxf(mt0, __shfl_xor_sync(0xffffffffu, mt0, 1));
        mt0 = fmaxf(mt0, __shfl_xor_sync(0xffffffffu, mt0, 2));
        mt1 = fmaxf(mt1, __shfl_xor_sync(0xffffffffu, mt1, 1));
        mt1 = fmaxf(mt1, __shfl_xor_sync(0xffffffffu, mt1, 2));

        float mn0 = fmaxf(m0, mt0), mn1 = fmaxf(m1, mt1);
        float al0 = __expf(m0 - mn0), al1 = __expf(m1 - mn1);
        m0 = mn0; m1 = mn1;

        float rs0 = 0.0f, rs1 = 0.0f;
#pragma unroll
        for (int nt = 0; nt < 8; nt++) {
            sc[nt][0] = __expf(sc[nt][0] - mn0);
            sc[nt][1] = __expf(sc[nt][1] - mn0);
            sc[nt][2] = __expf(sc[nt][2] - mn1);
            sc[nt][3] = __expf(sc[nt][3] - mn1);
            rs0 += sc[nt][0] + sc[nt][1];
            rs1 += sc[nt][2] + sc[nt][3];
        }
        rs0 += __shfl_xor_sync(0xffffffffu, rs0, 1);
        rs0 += __shfl_xor_sync(0xffffffffu, rs0, 2);
        rs1 += __shfl_xor_sync(0xffffffffu, rs1, 1);
        rs1 += __shfl_xor_sync(0xffffffffu, rs1, 2);
        l0 = l0 * al0 + rs0;
        l1 = l1 * al1 + rs1;

#pragma unroll
        for (int nt = 0; nt < 8; nt++) {
            acc[nt][0] *= al0; acc[nt][1] *= al0;
            acc[nt][2] *= al1; acc[nt][3] *= al1;
        }

#pragma unroll
        for (int ks = 0; ks < 4; ks++) {
            uint32_t ph[4], pl2[4];
            split2(sc[2 * ks][0],     sc[2 * ks][1],     ph[0], pl2[0]);
            split2(sc[2 * ks][2],     sc[2 * ks][3],     ph[1], pl2[1]);
            split2(sc[2 * ks + 1][0], sc[2 * ks + 1][1], ph[2], pl2[2]);
            split2(sc[2 * ks + 1][2], sc[2 * ks + 1][3], ph[3], pl2[3]);
            int pa = ks * 8 + lq, pb = pa + 4;
#pragma unroll
            for (int nt = 0; nt < 8; nt++) {
                int n = nt * 8 + lr;
                uint32_t vh2[2] = { sVh[SWZ64(pa, n)], sVh[SWZ64(pb, n)] };
                uint32_t vl2[2] = { sVl[SWZ64(pa, n)], sVl[SWZ64(pb, n)] };
                MMA_BF16(acc[nt], ph,  vl2);
                MMA_BF16(acc[nt], pl2, vh2);
                MMA_BF16(acc[nt], ph,  vh2);
            }
        }
    }

    const float inv0 = 1.0f / l0;
    const float inv1 = 1.0f / l1;
    const size_t pb0 = (size_t)(b * S_ + r0g)     * (D_ / 2) + h * (DK_ / 2);
    const size_t pb1 = (size_t)(b * S_ + r0g + 8) * (D_ / 2) + h * (DK_ / 2);
#pragma unroll
    for (int nt = 0; nt < 8; nt++) {
        int c = nt * 8 + 2 * lq;
        float o00 = acc[nt][0] * inv0, o01 = acc[nt][1] * inv0;
        float o10 = acc[nt][2] * inv1, o11 = acc[nt][3] * inv1;
        if (r0g == 0) { o00 = 0.0f; o01 = 0.0f; }
        uint32_t th, tl;
        split2(o00, o01, th, tl);
        ctxh[pb0 + (c >> 1)] = th; ctxl[pb0 + (c >> 1)] = tl;
        split2(o10, o11, th, tl);
        ctxh[pb1 + (c >> 1)] = th; ctxl[pb1 + (c >> 1)] = tl;
    }
}

// ---------------------------------------------------------------------------
// xout = LayerNorm(xin + res) * g + beta   (fp32 + planes)
// ---------------------------------------------------------------------------
__global__ void __launch_bounds__(128)
add_ln_kernel(const float* __restrict__ xin,
              const float* __restrict__ res,
              const float* __restrict__ g,
              const float* __restrict__ beta,
              float* __restrict__ xout,
              uint32_t* __restrict__ xh, uint32_t* __restrict__ xl)
{
    const int row = blockIdx.x;
    const int tid = threadIdx.x;

    float4 a = ((const float4*)(xin + (size_t)row * D_))[tid];
    float4 b = ((const float4*)(res + (size_t)row * D_))[tid];
    float v0 = a.x + b.x, v1 = a.y + b.y, v2 = a.z + b.z, v3 = a.w + b.w;

    float s  = v0 + v1 + v2 + v3;
    float sq = v0 * v0 + v1 * v1 + v2 * v2 + v3 * v3;
#pragma unroll
    for (int off = 16; off >= 1; off >>= 1) {
        s  += __shfl_xor_sync(0xffffffffu, s,  off);
        sq += __shfl_xor_sync(0xffffffffu, sq, off);
    }
    __shared__ float ss[4], ssq[4];
    int w = tid >> 5, lane = tid & 31;
    if (lane == 0) { ss[w] = s; ssq[w] = sq; }
    __syncthreads();
    s  = ss[0]  + ss[1]  + ss[2]  + ss[3];
    sq = ssq[0] + ssq[1] + ssq[2] + ssq[3];

    const float mu   = s * (1.0f / (float)D_);
    const float var  = sq * (1.0f / (float)D_) - mu * mu;
    const float rstd = rsqrtf(var + 1e-5f);

    float4 gg = ((const float4*)g)[tid];
    float4 bb = ((const float4*)beta)[tid];
    float4 o;
    o.x = (v0 - mu) * rstd * gg.x + bb.x;
    o.y = (v1 - mu) * rstd * gg.y + bb.y;
    o.z = (v2 - mu) * rstd * gg.z + bb.z;
    o.w = (v3 - mu) * rstd * gg.w + bb.w;
    ((float4*)(xout + (size_t)row * D_))[tid] = o;

    uint32_t h, l;
    size_t pidx = (size_t)row * (D_ / 2) + tid * 2;
    split2(o.x, o.y, h, l); xh[pidx] = h;     xl[pidx] = l;
    split2(o.z, o.w, h, l); xh[pidx + 1] = h; xl[pidx + 1] = l;
}

// ---------------------------------------------------------------------------
// Orchestration
// ---------------------------------------------------------------------------
extern "C" void kernel_launch(void* const* d_in, const int* in_sizes, int n_in,
                              void* d_out, int out_size)
{
    const float* q   = (const float*)d_in[0];
    const float* qa  = (const float*)d_in[1];
    const float* fr  = (const float*)d_in[2];
    const float* pe  = (const float*)d_in[3];
    const float* Wk  = (const float*)d_in[4];
    const float* bk  = (const float*)d_in[5];
    const float* Wv  = (const float*)d_in[6];
    const float* bv  = (const float*)d_in[7];
    const float* Wo  = (const float*)d_in[8];
    const float* bo  = (const float*)d_in[9];
    const float* W1  = (const float*)d_in[10];
    const float* b1  = (const float*)d_in[11];
    const float* W2  = (const float*)d_in[12];
    const float* b2  = (const float*)d_in[13];
    const float* g1  = (const float*)d_in[14];
    const float* be1 = (const float*)d_in[15];
    const float* g2  = (const float*)d_in[16];
    const float* be2 = (const float*)d_in[17];
    float* out = (float*)d_out;

    float *x, *kqb, *vb, *ob;
    uint32_t *xh, *xl, *yh, *yl, *ch, *cl, *hh, *hl, *wAh, *wAl;
    cudaGetSymbolAddress((void**)&x,   g_x);
    cudaGetSymbolAddress((void**)&kqb, g_kq);
    cudaGetSymbolAddress((void**)&vb,  g_v);
    cudaGetSymbolAddress((void**)&ob,  g_o);
    cudaGetSymbolAddress((void**)&xh,  g_xh);
    cudaGetSymbolAddress((void**)&xl,  g_xl);
    cudaGetSymbolAddress((void**)&yh,  g_yh);
    cudaGetSymbolAddress((void**)&yl,  g_yl);
    cudaGetSymbolAddress((void**)&ch,  g_ch);
    cudaGetSymbolAddress((void**)&cl,  g_cl);
    cudaGetSymbolAddress((void**)&hh,  g_hh);
    cudaGetSymbolAddress((void**)&hl,  g_hl);
    cudaGetSymbolAddress((void**)&wAh, g_wAh);
    cudaGetSymbolAddress((void**)&wAl, g_wAl);

    conv_w_kernel<<<LDDP / 256, 256>>>((const float2*)Wk, wAh,            wAl,            LDDP);
    conv_w_kernel<<<LDDP / 256, 256>>>((const float2*)Wv, wAh + LDDP,     wAl + LDDP,     LDDP);
    conv_w_kernel<<<LDDP / 256, 256>>>((const float2*)Wo, wAh + 2 * LDDP, wAl + 2 * LDDP, LDDP);
    conv_w_kernel<<<LFDP / 256, 256>>>((const float2*)W1, wAh + 3 * LDDP, wAl + 3 * LDDP, LFDP);
    conv_w_kernel<<<LFDP / 256, 256>>>((const float2*)W2, wAh + 3 * LDDP + LFDP,
                                                          wAl + 3 * LDDP + LFDP, LFDP);

    {
        int n4 = MROWS * D_ / 4;
        add_pos_kernel<<<(n4 + 255) / 256, 256>>>(
            (const float4*)q, (const float4*)qa, (const float4*)pe,
            (float4*)x, xh, xl, yh, yl);
    }

    const dim3 gD (D_ / 128, MROWS / 128);     // (4, 128)
    const dim3 gD2(D_ / 128, MROWS / 128, 2);  // (4, 128, 2) dual
    const dim3 gF (F_ / 128, MROWS / 128);     // (16, 128)
    const dim3 gA (S_ / 128, H_, B_);          // (4, 8, 32)
    const int  pDD = D_ * D_ / 2;
    const int  pFD = F_ * D_ / 2;

    for (int l = 0; l < L_; l++) {
        const uint32_t* kWh = wAh + (size_t)l * pDD;
        const uint32_t* kWl = wAl + (size_t)l * pDD;
        const uint32_t* vWh = wAh + LDDP + (size_t)l * pDD;
        const uint32_t* vWl = wAl + LDDP + (size_t)l * pDD;
        const uint32_t* oWh = wAh + 2 * LDDP + (size_t)l * pDD;
        const uint32_t* oWl = wAl + 2 * LDDP + (size_t)l * pDD;
        const uint32_t* w1h = wAh + 3 * LDDP + (size_t)l * pFD;
        const uint32_t* w1l = wAl + 3 * LDDP + (size_t)l * pFD;
        const uint32_t* w2h = wAh + 3 * LDDP + LFDP + (size_t)l * pFD;
        const uint32_t* w2l = wAl + 3 * LDDP + LFDP + (size_t)l * pFD;

        // merged kq + v projections (independent): one launch, packed waves
        gemm_cp_dual_kernel<<<gD2, 256>>>(
            xh, xl, kWh, kWl, bk + l * D_, kqb,
            yh, yl, vWh, vWl, bv + l * D_, vb, D_, D_);
        attn_tc_kernel<<<gA, 256>>>(kqb, vb, fr, ch, cl);
        gemm_cp_kernel<0><<<gD, 256>>>(ch, cl, oWh, oWl, bo + l * D_,
                                       ob, nullptr, nullptr, MROWS, D_, D_);
        add_ln_kernel<<<MROWS, 128>>>(x, ob, g1 + l * D_, be1 + l * D_, x, xh, xl);
        gemm_cp_kernel<1><<<gF, 256>>>(xh, xl, w1h, w1l, b1 + l * F_,
                                       nullptr, hh, hl, MROWS, F_, D_);
        gemm_cp_kernel<0><<<gD, 256>>>(hh, hl, w2h, w2l, b2 + l * D_,
                                       ob, nullptr, nullptr, MROWS, D_, F_);
        add_ln_kernel<<<MROWS, 128>>>(x, ob, g2 + l * D_, be2 + l * D_,
                                      (l == L_ - 1) ? out : x, xh, xl);
    }
}